// round 1
// baseline (speedup 1.0000x reference)
#include <cuda_runtime.h>
#include <cuda_bf16.h>

// Box-sum 8x8 stride 4 over (8,32,512,512) fp32 NCHW -> (8,32,127,127).
// Decomposition: G[g][ox] = sum over input rows [4g,4g+4) and cols [4ox,4ox+8).
// out[r][ox] = G[r][ox] + G[r+1][ox].  Each block streams one vertical band of
// one plane, loading each input row exactly once (within the band), staging
// 4 rows (8KB) in smem per group.

#define IN_H 512
#define IN_W 512
#define OUT_H 127
#define OUT_W 127
#define BAND 32          // output rows per block band
#define THREADS 128

__global__ __launch_bounds__(THREADS)
void boxsum8s4_kernel(const float* __restrict__ x, float* __restrict__ y) {
    __shared__ __align__(16) float s[4 * IN_W];   // 4 staged input rows, 8 KB

    const int plane = blockIdx.x;          // 0..255  (n*32 + c)
    const int band  = blockIdx.y;          // 0..3
    const int r0 = band * BAND;
    const int r1 = min(r0 + BAND, OUT_H);  // outputs [r0, r1)

    const int tid = threadIdx.x;           // 0..127

    const float* xp = x + (size_t)plane * IN_H * IN_W;
    float*       yp = y + (size_t)plane * OUT_H * OUT_W;

    float prevG = 0.0f;

    // Groups g = r0 .. r1 inclusive; group g covers input rows [4g, 4g+4).
    for (int g = r0; g <= r1; ++g) {
        // ---- stage 4 input rows into smem (fully coalesced float4) ----
        const float4* src = (const float4*)(xp + (size_t)(4 * g) * IN_W);
        float4*       dst = (float4*)s;
        #pragma unroll
        for (int ry = 0; ry < 4; ++ry) {
            dst[ry * (IN_W / 4) + tid] = src[ry * (IN_W / 4) + tid];
        }
        __syncthreads();

        // ---- per-thread group sum: 4 rows x 8 cols starting at 4*tid ----
        float G = 0.0f;
        if (tid < OUT_W) {
            #pragma unroll
            for (int ry = 0; ry < 4; ++ry) {
                const float* row = s + ry * IN_W + 4 * tid;
                float4 a = *(const float4*)(row);       // cols 4t..4t+3 (16B aligned)
                float4 b = *(const float4*)(row + 4);   // cols 4t+4..4t+7
                G += (a.x + a.y) + (a.z + a.w) + (b.x + b.y) + (b.z + b.w);
            }
            if (g > r0) {
                yp[(size_t)(g - 1) * OUT_W + tid] = prevG + G;
            }
        }
        prevG = G;
        __syncthreads();   // protect smem before next group's fill
    }
}

extern "C" void kernel_launch(void* const* d_in, const int* in_sizes, int n_in,
                              void* d_out, int out_size) {
    const float* x = (const float*)d_in[0];
    float* y = (float*)d_out;
    dim3 grid(8 * 32, (OUT_H + BAND - 1) / BAND);   // 256 planes x 4 bands
    boxsum8s4_kernel<<<grid, THREADS>>>(x, y);
}